// round 13
// baseline (speedup 1.0000x reference)
#include <cuda_runtime.h>

// Permutation: out[b,i,j,W,p,q] = x[b, 2i+p, 2j+q, W]   (k=2 unfold repack)
// x: (16, 64, 224, 224) fp32 -> pure streaming permutation, HBM-bound.
//
// R13: smem-free variant. Each 4-lane quad performs the 4x4 interleave as
// a register transpose (4x shfl.bfly). Lane r loads one float4 from source
// row r (rows (p,q) = (r>>1, r&1)); after the transpose lane r holds the
// finished output float4 for W = 4g + r. Warp load = 4x 128B lines per
// LDG.128; warp store = 512B contiguous. No smem, no __syncthreads.
//
// Block = 4 segments, 224 threads (7 warps x 4 iterations = 28 warp-tiles
// of 8 W-groups each = 4 x 56 groups).

#define H 224
#define W_DIM 224
#define C 64
#define JN 112          // h/2
#define IN 32           // c/2
#define W4 56           // W_DIM/4 float4 per row
#define THREADS 224
#define GRID 14336      // 57344 segments / 4

__global__ void __launch_bounds__(THREADS) KernelActivation_perm13(
    const float4* __restrict__ x4, float4* __restrict__ out4)
{
    const int tid  = threadIdx.x;
    const int warp = tid >> 5;
    const int lane = tid & 31;
    const int k8   = lane >> 2;     // quad id within warp, 0..7
    const int r    = lane & 3;      // lane within quad = source row id
    const int seg4 = blockIdx.x * 4;
    const unsigned FULL = 0xFFFFFFFFu;

#pragma unroll
    for (int it = 0; it < 4; it++) {
        const int u     = warp * 4 + it;    // 0..27 warp-tile index
        const int sl    = u / 7;            // local segment 0..3
        const int chunk = u % 7;            // 8-group chunk 0..6
        const int seg   = seg4 + sl;

        const int j = seg % JN;
        const int t = seg / JN;
        const int i = t & (IN - 1);
        const int b = t >> 5;

        // source row for this lane: x[b, 2i + (r>>1), 2j + (r&1), :]
        const int row = (b * C + 2 * i + (r >> 1)) * H + 2 * j + (r & 1);
        const int g   = 8 * chunk + k8;     // W-group 0..55

        const float4 v = __ldcs(&x4[row * W4 + g]);

        // 4x4 transpose across the quad: x_c starts as row r, W=4g+c;
        // ends as row c, W=4g+r.
        float x0 = v.x, x1 = v.y, x2 = v.z, x3 = v.w;

        float t0 = __shfl_xor_sync(FULL, (r & 1) ? x0 : x1, 1);
        float t1 = __shfl_xor_sync(FULL, (r & 1) ? x2 : x3, 1);
        if (r & 1) { x0 = t0; x2 = t1; } else { x1 = t0; x3 = t1; }

        float s0 = __shfl_xor_sync(FULL, (r & 2) ? x0 : x2, 2);
        float s1 = __shfl_xor_sync(FULL, (r & 2) ? x1 : x3, 2);
        if (r & 2) { x0 = s0; x1 = s1; } else { x2 = s0; x3 = s1; }

        // output float4 for (seg, W = 4g + r): rows in (p,q) order
        // = (x0, x1, x2, x3). Warp store: f = seg*224 + 32*chunk + lane
        // -> 32 consecutive float4 = 512B contiguous.
        __stcs(&out4[seg * W_DIM + 32 * chunk + lane],
               make_float4(x0, x1, x2, x3));
    }
}

extern "C" void kernel_launch(void* const* d_in, const int* in_sizes, int n_in,
                              void* d_out, int out_size)
{
    const float4* x4 = (const float4*)d_in[0];
    float4* out4 = (float4*)d_out;
    KernelActivation_perm13<<<GRID, THREADS>>>(x4, out4);
}

// round 14
// speedup vs baseline: 1.0528x; 1.0528x over previous
#include <cuda_runtime.h>

// Permutation: out[b,i,j,W,p,q] = x[b, 2i+p, 2j+q, W]   (k=2 unfold repack)
// x: (16, 64, 224, 224) fp32 -> pure streaming permutation, HBM-bound.
//
// FINAL (R9, twice-confirmed best wall 63.5/63.7us of a 14-bench series
// converged at the B300 1:1 R/W HBM ceiling, ~6.0-6.3 TB/s effective).
//  - 8 segments per block, 448 threads, one-shot grid of 7168 blocks
//  - loads : 4x LDG.128 per thread (front-batched, MLP=4), 512B/warp,
//            __ldcs streaming
//  - smem  : XOR swizzle g(f) = f ^ ((f>>3)&7) (float4 units) ->
//            conflict-free for BOTH the stride-4 STS interleave and
//            the stride-1 LDS drain; smem decouples load/store streams
//  - stores: contiguous 28672B run per block, STG.128 + __stcs
// Rejected by measurement: TMA bulk in/out (DRAM +1%, wall neutral,
// occ/tail costs), persistent grid (wave imbalance), write-back stores,
// L2::256B hints, forced residency, smem-free shfl transpose (MLP
// collapse, -4us).

#define H 224
#define W_DIM 224
#define C 64
#define JN 112          // h/2
#define IN 32           // c/2
#define W4 56           // W_DIM/4 float4 per row
#define SEGB 8          // segments per block
#define THREADS 448     // SEGB * W4
#define GRID 7168       // 57344 / SEGB

__device__ __forceinline__ int sw(int f) { return f ^ ((f >> 3) & 7); }

__global__ void __launch_bounds__(THREADS) KernelActivation_final(
    const float4* __restrict__ x4, float4* __restrict__ out4)
{
    __shared__ float4 s[SEGB * W_DIM];   // 28672 B

    const int tid  = threadIdx.x;
    const int sl   = tid / W4;           // 0..7 local segment
    const int wg   = tid % W4;           // 0..55 float4 group in row
    const int seg0 = blockIdx.x * SEGB;
    const int seg  = seg0 + sl;

    const int j = seg % JN;
    const int t = seg / JN;
    const int i = t & (IN - 1);
    const int b = t >> 5;

    // x[b, 2i+p, 2j+q, :] rows (float4 units)
    const int base = ((b * C + 2 * i) * H + 2 * j) * W4 + wg;

    const float4 r00 = __ldcs(&x4[base]);                 // p=0 q=0
    const float4 r01 = __ldcs(&x4[base + W4]);            // p=0 q=1
    const float4 r10 = __ldcs(&x4[base + H * W4]);        // p=1 q=0
    const float4 r11 = __ldcs(&x4[base + H * W4 + W4]);   // p=1 q=1

    // STS: f = 4*tid + m, swizzled -> conflict-free
    const int f0 = 4 * tid;
    s[sw(f0 + 0)] = make_float4(r00.x, r01.x, r10.x, r11.x);
    s[sw(f0 + 1)] = make_float4(r00.y, r01.y, r10.y, r11.y);
    s[sw(f0 + 2)] = make_float4(r00.z, r01.z, r10.z, r11.z);
    s[sw(f0 + 3)] = make_float4(r00.w, r01.w, r10.w, r11.w);

    __syncthreads();

    // drain: contiguous 28672B block store, LDS swizzled -> conflict-free
    float4* dst = &out4[(long)seg0 * W_DIM];
#pragma unroll
    for (int m = 0; m < 4; m++) {
        const int f = m * THREADS + tid;
        __stcs(&dst[f], s[sw(f)]);
    }
}

extern "C" void kernel_launch(void* const* d_in, const int* in_sizes, int n_in,
                              void* d_out, int out_size)
{
    const float4* x4 = (const float4*)d_in[0];
    float4* out4 = (float4*)d_out;
    KernelActivation_final<<<GRID, THREADS>>>(x4, out4);
}